// round 12
// baseline (speedup 1.0000x reference)
#include <cuda_runtime.h>
#include <cuda_fp16.h>
#include <stdint.h>

// ===========================================================================
// Problem constants
// ===========================================================================
static constexpr int  Dd    = 384;
static constexpr long KTOT  = 147456;             // D*D

// Wide GEMM tiling (legacy HMMA path: mma.sync.m16n8k16, f32 accum)
static constexpr int PF     = 5;                  // prefetch distance (ring depth 6)

// K-split: 16 slices of 24 p-values (144 chunks of 64 k) each
static constexpr int KSPLIT = 16;
static constexpr int PSLICE = Dd / KSPLIT;        // 24
static constexpr int CPER   = PSLICE * 6;         // 144 chunks per unit
static constexpr int NWIDE  = 8 * 16 * KSPLIT;    // 2048 wide units
static constexpr int NDEEP  = 16 * 12;            // 192 deep tiles

// smem layout (dynamic):
//   [0, RINGB)              f32 staging ring: 6 slots x 48 rows x 272 B
//   [RINGB, +2*F16B)        f16 tile double buffer (48 rows x 128 B, swizzled)
//   [OFF_MBAR, +48)         6 mbarriers
static constexpr int SROW   = 272;                // padded f32 row (256 data + 16)
static constexpr int SSLOT  = 48 * SROW;          // 13056
static constexpr int RINGB  = 6 * SSLOT;          // 78336
static constexpr int F16B   = 48 * 128;           // 6144
static constexpr int OFF_F16  = RINGB;
static constexpr int OFF_MBAR = RINGB + 2 * F16B; // 90624
static constexpr int SMEM_TOTAL = OFF_MBAR + 64;  // 90688

// per-K-slice partial accumulators (deterministic, no atomics): [16][1024][768]
__device__ __align__(16) float g_part[KSPLIT * 1024 * 768];

// ===========================================================================
// PTX helpers (baseline compute_103 features only: sm_90-era, no 'a')
// ===========================================================================
static __device__ __forceinline__ uint32_t smem_u32(const void* p) {
    uint32_t a;
    asm("{ .reg .u64 t; cvta.to.shared.u64 t, %1; cvt.u32.u64 %0, t; }" : "=r"(a) : "l"(p));
    return a;
}

#define MBAR_INIT(mbar, cnt) \
    asm volatile("mbarrier.init.shared.b64 [%0], %1;" \
                 :: "r"((uint32_t)(mbar)), "r"((uint32_t)(cnt)) : "memory")

#define MBAR_EXPECT_TX(mbar, bytes) \
    asm volatile("mbarrier.arrive.expect_tx.shared.b64 _, [%0], %1;" \
                 :: "r"((uint32_t)(mbar)), "r"((uint32_t)(bytes)) : "memory")

static __device__ __forceinline__ void mbar_wait(uint32_t mbar, uint32_t parity) {
    asm volatile(
        "{\n\t.reg .pred P;\n\t"
        "WL%=:\n\t"
        "mbarrier.try_wait.parity.acquire.cta.shared::cta.b64 P, [%0], %1;\n\t"
        "@!P bra WL%=;\n\t"
        "}"
        :: "r"(mbar), "r"(parity) : "memory");
}

static __device__ __forceinline__ void bulk_copy(uint32_t dst_smem, const void* src,
                                                 uint32_t bytes, uint32_t mbar) {
    asm volatile(
        "cp.async.bulk.shared::cta.global.mbarrier::complete_tx::bytes [%0], [%1], %2, [%3];"
        :: "r"(dst_smem), "l"(src), "r"(bytes), "r"(mbar) : "memory");
}

#define FENCE_PROXY_ASYNC() asm volatile("fence.proxy.async.shared::cta;" ::: "memory")

#define LDSM_X4(b0, b1, b2, b3, addr) \
    asm volatile("ldmatrix.sync.aligned.m8n8.x4.shared.b16 {%0,%1,%2,%3}, [%4];" \
                 : "=r"(b0), "=r"(b1), "=r"(b2), "=r"(b3) : "r"(addr))

#define MMA16816(d, a0, a1, a2, a3, b0, b1) \
    asm volatile("mma.sync.aligned.m16n8k16.row.col.f32.f16.f16.f32 " \
                 "{%0,%1,%2,%3}, {%4,%5,%6,%7}, {%8,%9}, {%0,%1,%2,%3};" \
                 : "+f"((d)[0]), "+f"((d)[1]), "+f"((d)[2]), "+f"((d)[3]) \
                 : "r"(a0), "r"(a1), "r"(a2), "r"(a3), "r"(b0), "r"(b1))

static __device__ __forceinline__ uint32_t h2u(__half2 v) {
    return *reinterpret_cast<uint32_t*>(&v);
}

// ===========================================================================
// Fused kernel: blocks [0,2048) = wide units, [2048,2240) = deep tiles.
//   Wide unit = (mt, nt, ksl): m-tile 128, n-tile 48, p in [ksl*24,(ksl+1)*24)
//   B loaded as f32 directly from W_L2 (per-row bulk copies), converted to
//   swizzled f16 in smem in-kernel. Partials -> g_part[ksl].
//   Deep tile = exact f32 64x64 SGEMM into out[:, 0:768].
// ===========================================================================
__global__ __launch_bounds__(256, 1) void fused_kernel(const float* __restrict__ hs,
                                                       const float* __restrict__ ht,
                                                       const float* __restrict__ WL,
                                                       const float* __restrict__ bL,
                                                       const float* __restrict__ WL2,
                                                       float* __restrict__ out) {
    extern __shared__ __align__(16) char smem[];

    const int tid = threadIdx.x;

    if (blockIdx.x >= NWIDE) {
        // ------------------ deep path tile ------------------
        float* As = reinterpret_cast<float*>(smem);          // [16][64]
        float* Bs = As + 16 * 64;                            // [16][64]
        const int t  = blockIdx.x - NWIDE;
        const int m0 = (t & 15) * 64;
        const int n0 = (t >> 4) * 64;
        const int ty = tid >> 4;
        const int tx = tid & 15;

        float acc[4][4] = {};

        for (int kk = 0; kk < 768; kk += 16) {
#pragma unroll
            for (int l = 0; l < 4; l++) {
                int i = tid + l * 256;
                int r = i >> 4;
                int c = i & 15;
                int k = kk + c;
                float av = (k < 384) ? hs[(size_t)(m0 + r) * 384 + k]
                                     : ht[(size_t)(m0 + r) * 384 + (k - 384)];
                As[c * 64 + r] = av;
                Bs[c * 64 + r] = WL[(size_t)(n0 + r) * 768 + k];
            }
            __syncthreads();
#pragma unroll
            for (int k = 0; k < 16; k++) {
                float4 a4 = *reinterpret_cast<const float4*>(&As[k * 64 + ty * 4]);
                float4 b4 = *reinterpret_cast<const float4*>(&Bs[k * 64 + tx * 4]);
                float a[4] = {a4.x, a4.y, a4.z, a4.w};
                float b[4] = {b4.x, b4.y, b4.z, b4.w};
#pragma unroll
                for (int i2 = 0; i2 < 4; i2++)
#pragma unroll
                    for (int j = 0; j < 4; j++) acc[i2][j] += a[i2] * b[j];
            }
            __syncthreads();
        }

#pragma unroll
        for (int i2 = 0; i2 < 4; i2++) {
            int m = m0 + ty * 4 + i2;
#pragma unroll
            for (int j = 0; j < 4; j++) {
                int n = n0 + tx * 4 + j;
                out[(size_t)m * 1536 + n] = acc[i2][j] + bL[n];
            }
        }
        return;
    }

    // ------------------ wide unit ------------------
    const int wid  = tid >> 5;
    const int lane = tid & 31;

    // blockIdx = ((ksl*16 + nt)*8 + mt): consecutive ids share the B slice
    const int mt   = blockIdx.x & 7;
    const int rest = blockIdx.x >> 3;
    const int nt   = rest & 15;
    const int ksl  = rest >> 4;
    const int n0   = nt * 48;
    const int p0   = ksl * PSLICE;

    // this thread's two A rows (mma m16n8k16 fragment rows)
    const int r0 = mt * 128 + wid * 16 + (lane >> 2);
    const int r1 = r0 + 8;
    const int qo = 2 * (lane & 3);           // fragment k offset within k16

    const uint32_t ring0 = smem_u32(smem);
    const uint32_t f16b  = smem_u32(smem + OFF_F16);
    const uint32_t mb0   = smem_u32(smem + OFF_MBAR);

    if (tid == 0) {
#pragma unroll
        for (int s = 0; s < 6; s++) MBAR_INIT(mb0 + s * 8, 1);
    }
    FENCE_PROXY_ASYNC();
    __syncthreads();

    // prologue: prefetch chunks 0..PF-1 (f32 rows) into ring slots 0..PF-1.
    // 4 lane-leaders in different warps issue 12 row-copies each; tx-count
    // semantics make expect/copy ordering races benign.
    if (lane == 0 && wid < 4) {
#pragma unroll
        for (int c = 0; c < PF; c++) {
            const uint32_t mb = mb0 + c * 8;
            if (wid == 0) MBAR_EXPECT_TX(mb, 12288);
            const long kb = (long)p0 * 384 + c * 64;
            const float* src = WL2 + (size_t)(n0 + wid * 12) * KTOT + kb;
            uint32_t dst = ring0 + c * SSLOT + (wid * 12) * SROW;
#pragma unroll
            for (int r = 0; r < 12; r++)
                bulk_copy(dst + r * SROW, src + (size_t)r * KTOT, 256, mb);
        }
    }

    // ---- resident ht fragments in registers: 2 rows x 24 blocks x 2 half2 ----
    __half2 htA[48], htB[48];
    {
        const float* htr0 = ht + (size_t)r0 * Dd;
        const float* htr1 = ht + (size_t)r1 * Dd;
#pragma unroll
        for (int blk = 0; blk < 24; blk++) {
            float2 f;
            f = *reinterpret_cast<const float2*>(htr0 + blk * 16 + qo);
            htA[blk * 2 + 0] = __floats2half2_rn(f.x, f.y);
            f = *reinterpret_cast<const float2*>(htr0 + blk * 16 + qo + 8);
            htA[blk * 2 + 1] = __floats2half2_rn(f.x, f.y);
            f = *reinterpret_cast<const float2*>(htr1 + blk * 16 + qo);
            htB[blk * 2 + 0] = __floats2half2_rn(f.x, f.y);
            f = *reinterpret_cast<const float2*>(htr1 + blk * 16 + qo + 8);
            htB[blk * 2 + 1] = __floats2half2_rn(f.x, f.y);
        }
    }

    float acc[6][4];
#pragma unroll
    for (int t = 0; t < 6; t++)
#pragma unroll
        for (int c = 0; c < 4; c++) acc[t][c] = 0.0f;

    // ldmatrix lane addressing (swizzled f16 tile): row base + seg^row XOR
    const uint32_t rowoff = (uint32_t)((lane & 7) * 128);
    const uint32_t x0 = (uint32_t)((((lane >> 3)    ) ^ (lane & 7)) * 16);
    const uint32_t x1 = (uint32_t)((((lane >> 3) + 4) ^ (lane & 7)) * 16);

    // convert-stage mapping (tid < 192): row r, quarter 'part' of 16 f32
    const int cvr = tid % 48;
    const int cvp = tid / 48;

    const float* hsr0 = hs + (size_t)r0 * Dd;
    const float* hsr1 = hs + (size_t)r1 * Dd;

    // ---- main loop: 24 p values x 6 chunks of 64 q ----
    for (int pp = 0; pp < PSLICE; pp++) {
        const int p = p0 + pp;
        __half2 h0 = __half2half2(__float2half_rn(__ldg(hsr0 + p)));
        __half2 h1 = __half2half2(__float2half_rn(__ldg(hsr1 + p)));
        const uint32_t par = (uint32_t)(pp & 1);

#pragma unroll
        for (int c2 = 0; c2 < 6; c2++) {
            const int cl = pp * 6 + c2;          // local chunk; slot == c2

            // all threads finished convert of chunk cl-1 => its ring slot and
            // its mbar phase are reusable; f16 buf (cl&1) free from cl-2.
            __syncthreads();

            // issue chunk cl+PF into slot (cl+PF)%6
            {
                const int nc = cl + PF;
                if (nc < CPER && lane == 0 && wid < 4) {
                    const int pn  = nc / 6;
                    const int c2n = nc - pn * 6;
                    const uint32_t mb = mb0 + c2n * 8;
                    if (wid == 0) MBAR_EXPECT_TX(mb, 12288);
                    const long kb = (long)(p0 + pn) * 384 + c2n * 64;
                    const float* src = WL2 + (size_t)(n0 + wid * 12) * KTOT + kb;
                    uint32_t dst = ring0 + c2n * SSLOT + (wid * 12) * SROW;
#pragma unroll
                    for (int r = 0; r < 12; r++)
                        bulk_copy(dst + r * SROW, src + (size_t)r * KTOT, 256, mb);
                }
            }

            // A fragments for 4 k16-steps (pure register math)
            uint32_t a[4][4];
#pragma unroll
            for (int s = 0; s < 4; s++) {
                const int blk = c2 * 4 + s;
                a[s][0] = h2u(__hmul2(h0, htA[blk * 2 + 0]));  // row r0, k lo
                a[s][1] = h2u(__hmul2(h1, htB[blk * 2 + 0]));  // row r1, k lo
                a[s][2] = h2u(__hmul2(h0, htA[blk * 2 + 1]));  // row r0, k hi
                a[s][3] = h2u(__hmul2(h1, htB[blk * 2 + 1]));  // row r1, k hi
            }

            // wait f32 staging for chunk cl
            mbar_wait(mb0 + c2 * 8, par);

            // convert f32 staging -> swizzled f16 tile (192 threads)
            const int fb = cl & 1;
            if (tid < 192) {
                const char* sp = smem + c2 * SSLOT + cvr * SROW + cvp * 64;
                float4 q0 = *reinterpret_cast<const float4*>(sp);
                float4 q1 = *reinterpret_cast<const float4*>(sp + 16);
                float4 q2 = *reinterpret_cast<const float4*>(sp + 32);
                float4 q3 = *reinterpret_cast<const float4*>(sp + 48);
                uint4 w0, w1;
                w0.x = h2u(__floats2half2_rn(q0.x, q0.y));
                w0.y = h2u(__floats2half2_rn(q0.z, q0.w));
                w0.z = h2u(__floats2half2_rn(q1.x, q1.y));
                w0.w = h2u(__floats2half2_rn(q1.z, q1.w));
                w1.x = h2u(__floats2half2_rn(q2.x, q2.y));
                w1.y = h2u(__floats2half2_rn(q2.z, q2.w));
                w1.z = h2u(__floats2half2_rn(q3.x, q3.y));
                w1.w = h2u(__floats2half2_rn(q3.z, q3.w));
                char* dp = smem + OFF_F16 + fb * F16B + cvr * 128;
                const int rx = cvr & 7;
                *reinterpret_cast<uint4*>(dp + (((cvp * 2)     ^ rx) << 4)) = w0;
                *reinterpret_cast<uint4*>(dp + (((cvp * 2 + 1) ^ rx) << 4)) = w1;
            }
            __syncthreads();   // f16 tile visible to all warps

            const uint32_t sbase = f16b + (uint32_t)(fb * F16B) + rowoff;
#pragma unroll
            for (int t = 0; t < 6; t++) {
                uint32_t b0, b1, b2, b3, b4, b5, b6, b7;
                LDSM_X4(b0, b1, b2, b3, sbase + (uint32_t)(t * 1024) + x0); // ksteps 0,1
                LDSM_X4(b4, b5, b6, b7, sbase + (uint32_t)(t * 1024) + x1); // ksteps 2,3
                MMA16816(acc[t], a[0][0], a[0][1], a[0][2], a[0][3], b0, b1);
                MMA16816(acc[t], a[1][0], a[1][1], a[1][2], a[1][3], b2, b3);
                MMA16816(acc[t], a[2][0], a[2][1], a[2][2], a[2][3], b4, b5);
                MMA16816(acc[t], a[3][0], a[3][1], a[3][2], a[3][3], b6, b7);
            }
        }
    }

    // ---- epilogue: store f32 partial into g_part[ksl] (deterministic) ----
    float* pb = g_part + (size_t)ksl * (1024 * 768);
#pragma unroll
    for (int t = 0; t < 6; t++) {
        const int n = n0 + t * 8 + qo;
        *reinterpret_cast<float2*>(pb + (size_t)r0 * 768 + n) =
            make_float2(acc[t][0], acc[t][1]);
        *reinterpret_cast<float2*>(pb + (size_t)r1 * 768 + n) =
            make_float2(acc[t][2], acc[t][3]);
    }
}

// ===========================================================================
// Reduce kernel: out[:,768:1536] = bias + sum over 16 K-slices of g_part
// grid = 768, block = 256; one float4 per thread (196608 float4 elements)
// ===========================================================================
__global__ __launch_bounds__(256) void reduce_kernel(const float* __restrict__ bL2,
                                                     float* __restrict__ out) {
    const int e4 = blockIdx.x * 256 + threadIdx.x;   // 0..196607
    const int b  = e4 / 192;                          // row
    const int n4 = e4 - b * 192;                      // float4 col
    const int n  = n4 * 4;

    float4 s = *reinterpret_cast<const float4*>(bL2 + n);
#pragma unroll
    for (int k = 0; k < KSPLIT; k++) {
        const float4 v = *reinterpret_cast<const float4*>(
            g_part + (size_t)k * (1024 * 768) + (size_t)b * 768 + n);
        s.x += v.x; s.y += v.y; s.z += v.z; s.w += v.w;
    }
    *reinterpret_cast<float4*>(out + (size_t)b * 1536 + 768 + n) = s;
}

// ===========================================================================
// kernel_launch
// Inputs (metadata order): hspatial, htext, W_L, b_L, W_L2, b_L2. Output f32.
// ===========================================================================
extern "C" void kernel_launch(void* const* d_in, const int* in_sizes, int n_in,
                              void* d_out, int out_size) {
    const float* hs  = (const float*)d_in[0];
    const float* ht  = (const float*)d_in[1];
    const float* WL  = (const float*)d_in[2];
    const float* bL  = (const float*)d_in[3];
    const float* WL2 = (const float*)d_in[4];
    const float* bL2 = (const float*)d_in[5];
    float* out = (float*)d_out;

    cudaFuncSetAttribute(fused_kernel, cudaFuncAttributeMaxDynamicSharedMemorySize,
                         SMEM_TOTAL);

    // 1) fused: 2048 wide K-slice units (HMMA, in-kernel f32->f16 convert)
    //    + 192 deep tiles
    fused_kernel<<<NWIDE + NDEEP, 256, SMEM_TOTAL>>>(hs, ht, WL, bL, WL2, out);

    // 2) reduce K-slice partials + bias into out
    reduce_kernel<<<768, 256>>>(bL2, out);
}

// round 13
// speedup vs baseline: 1.7533x; 1.7533x over previous
#include <cuda_runtime.h>
#include <cuda_fp16.h>
#include <stdint.h>

// ===========================================================================
// Problem constants
// ===========================================================================
static constexpr int  Dd    = 384;
static constexpr long KTOT  = 147456;             // D*D

// Wide GEMM tiling (legacy HMMA path: mma.sync.m16n8k16, f32 accum)
static constexpr int NCHUNK = 2304;               // KTOT / 64
static constexpr int DEPTH  = 6;                  // B ring depth (== chunks per p)
static constexpr int PF     = 5;                  // prefetch distance
static constexpr int TILEB  = 48 * 128;           // 6144 B per B tile (contiguous)

// K-split: 16 slices of 24 p-values (144 chunks) each
static constexpr int KSPLIT = 16;
static constexpr int PSLICE = Dd / KSPLIT;        // 24
static constexpr int NWIDE  = 8 * 16 * KSPLIT;    // 2048 wide units
static constexpr int NCONV  = 2048;               // convert blocks
static constexpr int NDEEP  = 16 * 12;            // 192 deep tiles

// fp16 copy of W_L2, TILED+SWIZZLED layout:
//   tile (T = n/48, c = chunk) at byte offset (T*NCHUNK + c)*6144
//   within tile: row r (=n%48), 16B seg s (=k/8 within chunk):
//   offset = r*128 + ((s ^ (r&7)) * 16)
__device__ __align__(16) __half g_W2h[113246208];

// per-K-slice partial accumulators (deterministic, no atomics): [16][1024][768]
__device__ __align__(16) float g_part[KSPLIT * 1024 * 768];

// ===========================================================================
// PTX helpers (baseline compute_103 features only: sm_90-era, no 'a')
// ===========================================================================
static __device__ __forceinline__ uint32_t smem_u32(const void* p) {
    uint32_t a;
    asm("{ .reg .u64 t; cvta.to.shared.u64 t, %1; cvt.u32.u64 %0, t; }" : "=r"(a) : "l"(p));
    return a;
}

#define MBAR_INIT(mbar, cnt) \
    asm volatile("mbarrier.init.shared.b64 [%0], %1;" \
                 :: "r"((uint32_t)(mbar)), "r"((uint32_t)(cnt)) : "memory")

#define MBAR_EXPECT_TX(mbar, bytes) \
    asm volatile("mbarrier.arrive.expect_tx.shared.b64 _, [%0], %1;" \
                 :: "r"((uint32_t)(mbar)), "r"((uint32_t)(bytes)) : "memory")

static __device__ __forceinline__ void mbar_wait(uint32_t mbar, uint32_t parity) {
    asm volatile(
        "{\n\t.reg .pred P;\n\t"
        "WL%=:\n\t"
        "mbarrier.try_wait.parity.acquire.cta.shared::cta.b64 P, [%0], %1;\n\t"
        "@!P bra WL%=;\n\t"
        "}"
        :: "r"(mbar), "r"(parity) : "memory");
}

static __device__ __forceinline__ void bulk_copy(uint32_t dst_smem, const void* src,
                                                 uint32_t bytes, uint32_t mbar) {
    asm volatile(
        "cp.async.bulk.shared::cta.global.mbarrier::complete_tx::bytes [%0], [%1], %2, [%3];"
        :: "r"(dst_smem), "l"(src), "r"(bytes), "r"(mbar) : "memory");
}

#define FENCE_PROXY_ASYNC() asm volatile("fence.proxy.async.shared::cta;" ::: "memory")

#define LDSM_X4(b0, b1, b2, b3, addr) \
    asm volatile("ldmatrix.sync.aligned.m8n8.x4.shared.b16 {%0,%1,%2,%3}, [%4];" \
                 : "=r"(b0), "=r"(b1), "=r"(b2), "=r"(b3) : "r"(addr))

#define MMA16816(d, a0, a1, a2, a3, b0, b1) \
    asm volatile("mma.sync.aligned.m16n8k16.row.col.f32.f16.f16.f32 " \
                 "{%0,%1,%2,%3}, {%4,%5,%6,%7}, {%8,%9}, {%0,%1,%2,%3};" \
                 : "+f"((d)[0]), "+f"((d)[1]), "+f"((d)[2]), "+f"((d)[3]) \
                 : "r"(a0), "r"(a1), "r"(a2), "r"(a3), "r"(b0), "r"(b1))

static __device__ __forceinline__ uint32_t h2u(__half2 v) {
    return *reinterpret_cast<uint32_t*>(&v);
}

// ===========================================================================
// Kernel 1 (prep): blocks [0,2048) convert W_L2 f32->f16 tiled+swizzled
// (DRAM-bound); blocks [2048,2240) run the deep path (FFMA-bound) — the two
// overlap on complementary pipes.
// ===========================================================================
__global__ __launch_bounds__(256) void prep_kernel(const float* __restrict__ W,
                                                   const float* __restrict__ hs,
                                                   const float* __restrict__ ht,
                                                   const float* __restrict__ WL,
                                                   const float* __restrict__ bL,
                                                   float* __restrict__ out) {
    const int tid = threadIdx.x;

    if (blockIdx.x < NCONV) {
        // ------------------ convert ------------------
        const long total = 768L * (KTOT / 8);          // 16B segs
        const long stride = (long)NCONV * 256;
        for (long g = (long)blockIdx.x * 256 + tid; g < total; g += stride) {
            int  n  = (int)(g / 18432);                // 18432 = KTOT/8
            int  ks = (int)(g - (long)n * 18432);
            int  c  = ks >> 3;
            int  s  = ks & 7;
            int  T  = n / 48;
            int  r  = n - T * 48;

            const float4* src = reinterpret_cast<const float4*>(
                W + (size_t)n * KTOT + ((size_t)c << 6) + (s << 3));
            float4 a = src[0];
            float4 b = src[1];
            uint4 v;
            v.x = h2u(__floats2half2_rn(a.x, a.y));
            v.y = h2u(__floats2half2_rn(a.z, a.w));
            v.z = h2u(__floats2half2_rn(b.x, b.y));
            v.w = h2u(__floats2half2_rn(b.z, b.w));

            size_t dst = (size_t)(T * NCHUNK + c) * TILEB
                       + (size_t)r * 128 + (size_t)((s ^ (r & 7)) << 4);
            *reinterpret_cast<uint4*>(reinterpret_cast<char*>(g_W2h) + dst) = v;
        }
        return;
    }

    // ------------------ deep path tile (exact f32 64x64 SGEMM) ------------------
    __shared__ float As[16][64];
    __shared__ float Bs[16][64];
    const int t  = blockIdx.x - NCONV;
    const int m0 = (t & 15) * 64;
    const int n0 = (t >> 4) * 64;
    const int ty = tid >> 4;
    const int tx = tid & 15;

    float acc[4][4] = {};

    for (int kk = 0; kk < 768; kk += 16) {
#pragma unroll
        for (int l = 0; l < 4; l++) {
            int i = tid + l * 256;
            int r = i >> 4;
            int c = i & 15;
            int k = kk + c;
            float av = (k < 384) ? hs[(size_t)(m0 + r) * 384 + k]
                                 : ht[(size_t)(m0 + r) * 384 + (k - 384)];
            As[c][r] = av;
            Bs[c][r] = WL[(size_t)(n0 + r) * 768 + k];
        }
        __syncthreads();
#pragma unroll
        for (int k = 0; k < 16; k++) {
            float4 a4 = *reinterpret_cast<const float4*>(&As[k][ty * 4]);
            float4 b4 = *reinterpret_cast<const float4*>(&Bs[k][tx * 4]);
            float a[4] = {a4.x, a4.y, a4.z, a4.w};
            float b[4] = {b4.x, b4.y, b4.z, b4.w};
#pragma unroll
            for (int i2 = 0; i2 < 4; i2++)
#pragma unroll
                for (int j = 0; j < 4; j++) acc[i2][j] += a[i2] * b[j];
        }
        __syncthreads();
    }

#pragma unroll
    for (int i2 = 0; i2 < 4; i2++) {
        int m = m0 + ty * 4 + i2;
#pragma unroll
        for (int j = 0; j < 4; j++) {
            int n = n0 + tx * 4 + j;
            out[(size_t)m * 1536 + n] = acc[i2][j] + bL[n];
        }
    }
}

// ===========================================================================
// Kernel 2: wide units (m-tile 128 x n-tile 48 x K-slice of 24 p-values)
//   A generated in registers; B via ONE cp.async.bulk per 64-k chunk.
//   f32 partials -> g_part[ksl] (deterministic, no atomics).
// ===========================================================================
__global__ __launch_bounds__(256, 1) void wide_kernel(const float* __restrict__ hs,
                                                      const float* __restrict__ ht,
                                                      float* __restrict__ outdummy) {
    __shared__ __align__(16) char ring[DEPTH][TILEB];        // 36864 B
    __shared__ __align__(8)  unsigned long long mbar[DEPTH];

    const int tid  = threadIdx.x;
    const int wid  = tid >> 5;
    const int lane = tid & 31;

    // blockIdx = ((ksl*16 + nt)*8 + mt): consecutive ids share the B slice
    const int mt   = blockIdx.x & 7;
    const int rest = blockIdx.x >> 3;
    const int nt   = rest & 15;
    const int ksl  = rest >> 4;
    const int n0   = nt * 48;
    const int p0   = ksl * PSLICE;
    const int CBEG = p0 * 6;
    const int CEND = (p0 + PSLICE) * 6;

    // this thread's two A rows (mma m16n8k16 fragment rows)
    const int r0 = mt * 128 + wid * 16 + (lane >> 2);
    const int r1 = r0 + 8;
    const int qo = 2 * (lane & 3);           // fragment k offset within k16

    const uint32_t ring0 = smem_u32(ring[0]);
    const uint32_t mb0   = smem_u32(&mbar[0]);

    if (tid == 0) {
#pragma unroll
        for (int s = 0; s < DEPTH; s++) MBAR_INIT(mb0 + s * 8, 1);
    }
    FENCE_PROXY_ASYNC();
    __syncthreads();

    // B tile source base for this n-tile (tiled+swizzled layout)
    const char* Wt = reinterpret_cast<const char*>(g_W2h) + (size_t)nt * NCHUNK * TILEB;

    // prologue: prefetch chunks CBEG..CBEG+PF-1 into slots 0..PF-1
    if (tid == 0) {
#pragma unroll
        for (int c = 0; c < PF; c++) {
            MBAR_EXPECT_TX(mb0 + c * 8, TILEB);
            bulk_copy(ring0 + c * TILEB, Wt + (size_t)(CBEG + c) * TILEB,
                      TILEB, mb0 + c * 8);
        }
    }

    // ---- resident ht fragments in registers: 2 rows x 24 blocks x 2 half2 ----
    __half2 htA[48], htB[48];
    {
        const float* htr0 = ht + (size_t)r0 * Dd;
        const float* htr1 = ht + (size_t)r1 * Dd;
#pragma unroll
        for (int blk = 0; blk < 24; blk++) {
            float2 f;
            f = *reinterpret_cast<const float2*>(htr0 + blk * 16 + qo);
            htA[blk * 2 + 0] = __floats2half2_rn(f.x, f.y);
            f = *reinterpret_cast<const float2*>(htr0 + blk * 16 + qo + 8);
            htA[blk * 2 + 1] = __floats2half2_rn(f.x, f.y);
            f = *reinterpret_cast<const float2*>(htr1 + blk * 16 + qo);
            htB[blk * 2 + 0] = __floats2half2_rn(f.x, f.y);
            f = *reinterpret_cast<const float2*>(htr1 + blk * 16 + qo + 8);
            htB[blk * 2 + 1] = __floats2half2_rn(f.x, f.y);
        }
    }

    float acc[6][4];
#pragma unroll
    for (int t = 0; t < 6; t++)
#pragma unroll
        for (int c = 0; c < 4; c++) acc[t][c] = 0.0f;

    // ldmatrix lane addressing (swizzled layout): row base + seg^row XOR
    const uint32_t rowoff = (uint32_t)((lane & 7) * 128);
    const uint32_t x0 = (uint32_t)((((lane >> 3)    ) ^ (lane & 7)) * 16);
    const uint32_t x1 = (uint32_t)((((lane >> 3) + 4) ^ (lane & 7)) * 16);

    const float* hsr0 = hs + (size_t)r0 * Dd;
    const float* hsr1 = hs + (size_t)r1 * Dd;

    // ---- main loop: 24 p values x 6 chunks of 64 q ----
    for (int pp = 0; pp < PSLICE; pp++) {
        const int p = p0 + pp;
        __half2 h0 = __half2half2(__float2half_rn(__ldg(hsr0 + p)));
        __half2 h1 = __half2half2(__float2half_rn(__ldg(hsr1 + p)));
        const uint32_t par = (uint32_t)(pp & 1);

#pragma unroll
        for (int c2 = 0; c2 < 6; c2++) {
            const int i = p * 6 + c2;            // global chunk; i % 6 == c2

            // all warps done with chunk i-1 => slot (i-1)%6 reusable
            __syncthreads();

            if (tid == 0) {
                int nc = i + PF;
                if (nc < CEND) {
                    int sl = (c2 + PF) % DEPTH;  // == nc % 6
                    MBAR_EXPECT_TX(mb0 + sl * 8, TILEB);
                    bulk_copy(ring0 + sl * TILEB, Wt + (size_t)nc * TILEB,
                              TILEB, mb0 + sl * 8);
                }
            }

            // A fragments for 4 k16-steps (pure register math)
            uint32_t a[4][4];
#pragma unroll
            for (int s = 0; s < 4; s++) {
                const int blk = c2 * 4 + s;
                a[s][0] = h2u(__hmul2(h0, htA[blk * 2 + 0]));  // row r0, k lo
                a[s][1] = h2u(__hmul2(h1, htB[blk * 2 + 0]));  // row r1, k lo
                a[s][2] = h2u(__hmul2(h0, htA[blk * 2 + 1]));  // row r0, k hi
                a[s][3] = h2u(__hmul2(h1, htB[blk * 2 + 1]));  // row r1, k hi
            }

            // wait B tile for chunk i
            mbar_wait(mb0 + c2 * 8, par);

            const uint32_t sbase = ring0 + (uint32_t)(c2 * TILEB) + rowoff;
#pragma unroll
            for (int t = 0; t < 6; t++) {
                uint32_t b0, b1, b2, b3, b4, b5, b6, b7;
                LDSM_X4(b0, b1, b2, b3, sbase + (uint32_t)(t * 1024) + x0); // ksteps 0,1
                LDSM_X4(b4, b5, b6, b7, sbase + (uint32_t)(t * 1024) + x1); // ksteps 2,3
                MMA16816(acc[t], a[0][0], a[0][1], a[0][2], a[0][3], b0, b1);
                MMA16816(acc[t], a[1][0], a[1][1], a[1][2], a[1][3], b2, b3);
                MMA16816(acc[t], a[2][0], a[2][1], a[2][2], a[2][3], b4, b5);
                MMA16816(acc[t], a[3][0], a[3][1], a[3][2], a[3][3], b6, b7);
            }
        }
    }

    // ---- epilogue: store f32 partial into g_part[ksl] (deterministic) ----
    float* pb = g_part + (size_t)ksl * (1024 * 768);
#pragma unroll
    for (int t = 0; t < 6; t++) {
        const int n = n0 + t * 8 + qo;
        *reinterpret_cast<float2*>(pb + (size_t)r0 * 768 + n) =
            make_float2(acc[t][0], acc[t][1]);
        *reinterpret_cast<float2*>(pb + (size_t)r1 * 768 + n) =
            make_float2(acc[t][2], acc[t][3]);
    }
}

// ===========================================================================
// Kernel 3: out[:,768:1536] = bias + sum over 16 K-slices of g_part
// grid = 768, block = 256; one float4 per thread (196608 float4 elements)
// ===========================================================================
__global__ __launch_bounds__(256) void reduce_kernel(const float* __restrict__ bL2,
                                                     float* __restrict__ out) {
    const int e4 = blockIdx.x * 256 + threadIdx.x;   // 0..196607
    const int b  = e4 / 192;                          // row
    const int n4 = e4 - b * 192;                      // float4 col
    const int n  = n4 * 4;

    float4 s = *reinterpret_cast<const float4*>(bL2 + n);
#pragma unroll
    for (int k = 0; k < KSPLIT; k++) {
        const float4 v = *reinterpret_cast<const float4*>(
            g_part + (size_t)k * (1024 * 768) + (size_t)b * 768 + n);
        s.x += v.x; s.y += v.y; s.z += v.z; s.w += v.w;
    }
    *reinterpret_cast<float4*>(out + (size_t)b * 1536 + 768 + n) = s;
}

// ===========================================================================
// kernel_launch
// Inputs (metadata order): hspatial, htext, W_L, b_L, W_L2, b_L2. Output f32.
// ===========================================================================
extern "C" void kernel_launch(void* const* d_in, const int* in_sizes, int n_in,
                              void* d_out, int out_size) {
    const float* hs  = (const float*)d_in[0];
    const float* ht  = (const float*)d_in[1];
    const float* WL  = (const float*)d_in[2];
    const float* bL  = (const float*)d_in[3];
    const float* WL2 = (const float*)d_in[4];
    const float* bL2 = (const float*)d_in[5];
    float* out = (float*)d_out;

    // 1) prep: convert W_L2 (DRAM-bound) overlapped with deep path (FFMA-bound)
    prep_kernel<<<NCONV + NDEEP, 256>>>(WL2, hs, ht, WL, bL, out);

    // 2) wide path: 2048 K-slice units (HMMA floor-bound)
    wide_kernel<<<NWIDE, 256>>>(hs, ht, out);

    // 3) reduce K-slice partials + bias
    reduce_kernel<<<768, 256>>>(bL2, out);
}

// round 14
// speedup vs baseline: 1.8746x; 1.0692x over previous
#include <cuda_runtime.h>
#include <cuda_fp16.h>
#include <stdint.h>

// ===========================================================================
// Problem constants
// ===========================================================================
static constexpr int  Dd    = 384;
static constexpr long KTOT  = 147456;             // D*D

// Wide GEMM tiling (legacy HMMA path: mma.sync.m16n8k16, f32 accum)
static constexpr int NCHUNK = 2304;               // KTOT / 64
static constexpr int DEPTH  = 6;                  // B ring depth (== chunks per p)
static constexpr int PF     = 5;                  // prefetch distance
static constexpr int TILEB  = 48 * 128;           // 6144 B per B tile (contiguous)

// K-split: 16 slices of 24 p-values (144 chunks) each
static constexpr int KSPLIT = 16;
static constexpr int PSLICE = Dd / KSPLIT;        // 24
static constexpr int NWIDE  = 8 * 16 * KSPLIT;    // 2048 wide units
static constexpr int NDEEP  = 16 * 12;            // 192 deep tiles

// fp16 copy of W_L2, TILED+SWIZZLED layout:
//   tile (T = n/48, c = chunk) at byte offset (T*NCHUNK + c)*6144
//   within tile: row r (=n%48), 16B seg s (=k/8 within chunk):
//   offset = r*128 + ((s ^ (r&7)) * 16)
__device__ __align__(16) __half g_W2h[113246208];

// per-K-slice partial accumulators (deterministic, no atomics): [16][1024][768]
__device__ __align__(16) float g_part[KSPLIT * 1024 * 768];

// ===========================================================================
// PTX helpers (baseline compute_103 features only: sm_90-era, no 'a')
// ===========================================================================
static __device__ __forceinline__ uint32_t smem_u32(const void* p) {
    uint32_t a;
    asm("{ .reg .u64 t; cvta.to.shared.u64 t, %1; cvt.u32.u64 %0, t; }" : "=r"(a) : "l"(p));
    return a;
}

#define MBAR_INIT(mbar, cnt) \
    asm volatile("mbarrier.init.shared.b64 [%0], %1;" \
                 :: "r"((uint32_t)(mbar)), "r"((uint32_t)(cnt)) : "memory")

#define MBAR_EXPECT_TX(mbar, bytes) \
    asm volatile("mbarrier.arrive.expect_tx.shared.b64 _, [%0], %1;" \
                 :: "r"((uint32_t)(mbar)), "r"((uint32_t)(bytes)) : "memory")

static __device__ __forceinline__ void mbar_wait(uint32_t mbar, uint32_t parity) {
    asm volatile(
        "{\n\t.reg .pred P;\n\t"
        "WL%=:\n\t"
        "mbarrier.try_wait.parity.acquire.cta.shared::cta.b64 P, [%0], %1;\n\t"
        "@!P bra WL%=;\n\t"
        "}"
        :: "r"(mbar), "r"(parity) : "memory");
}

static __device__ __forceinline__ void bulk_copy(uint32_t dst_smem, const void* src,
                                                 uint32_t bytes, uint32_t mbar) {
    asm volatile(
        "cp.async.bulk.shared::cta.global.mbarrier::complete_tx::bytes [%0], [%1], %2, [%3];"
        :: "r"(dst_smem), "l"(src), "r"(bytes), "r"(mbar) : "memory");
}

#define FENCE_PROXY_ASYNC() asm volatile("fence.proxy.async.shared::cta;" ::: "memory")

#define LDSM_X4(b0, b1, b2, b3, addr) \
    asm volatile("ldmatrix.sync.aligned.m8n8.x4.shared.b16 {%0,%1,%2,%3}, [%4];" \
                 : "=r"(b0), "=r"(b1), "=r"(b2), "=r"(b3) : "r"(addr))

#define MMA16816(d, a0, a1, a2, a3, b0, b1) \
    asm volatile("mma.sync.aligned.m16n8k16.row.col.f32.f16.f16.f32 " \
                 "{%0,%1,%2,%3}, {%4,%5,%6,%7}, {%8,%9}, {%0,%1,%2,%3};" \
                 : "+f"((d)[0]), "+f"((d)[1]), "+f"((d)[2]), "+f"((d)[3]) \
                 : "r"(a0), "r"(a1), "r"(a2), "r"(a3), "r"(b0), "r"(b1))

static __device__ __forceinline__ uint32_t h2u(__half2 v) {
    return *reinterpret_cast<uint32_t*>(&v);
}

// ===========================================================================
// Kernel 1: W_L2 f32 -> f16, TILED+SWIZZLED layout (pure streaming, 32 regs,
// high occupancy — measured 99 us @ 82% of HBM peak; do NOT fuse anything in)
// ===========================================================================
__global__ __launch_bounds__(256) void convert_kernel(const float* __restrict__ W) {
    const long total = 768L * (KTOT / 8);          // 16B segs
    const long stride = (long)gridDim.x * blockDim.x;
    for (long g = (long)blockIdx.x * blockDim.x + threadIdx.x; g < total; g += stride) {
        int  n  = (int)(g / 18432);                // 18432 = KTOT/8
        int  ks = (int)(g - (long)n * 18432);
        int  c  = ks >> 3;
        int  s  = ks & 7;
        int  T  = n / 48;
        int  r  = n - T * 48;

        const float4* src = reinterpret_cast<const float4*>(
            W + (size_t)n * KTOT + ((size_t)c << 6) + (s << 3));
        float4 a = src[0];
        float4 b = src[1];
        uint4 v;
        v.x = h2u(__floats2half2_rn(a.x, a.y));
        v.y = h2u(__floats2half2_rn(a.z, a.w));
        v.z = h2u(__floats2half2_rn(b.x, b.y));
        v.w = h2u(__floats2half2_rn(b.z, b.w));

        size_t dst = (size_t)(T * NCHUNK + c) * TILEB
                   + (size_t)r * 128 + (size_t)((s ^ (r & 7)) << 4);
        *reinterpret_cast<uint4*>(reinterpret_cast<char*>(g_W2h) + dst) = v;
    }
}

// ===========================================================================
// Kernel 2 (fused): blocks [0,2048) = wide units, [2048,2240) = deep tiles.
//   Occupancy-1 kernel: the deep branch's registers don't cost anything here.
//   Wide unit = (mt, nt, ksl): m-tile 128, n-tile 48, 24 p-values.
//   Deep tile = exact f32 64x64 SGEMM into out[:, 0:768].
// ===========================================================================
union SmemU {
    struct {
        char ring[DEPTH][TILEB];                 // 36864 B
        unsigned long long mbar[DEPTH];
    } w;
    struct {
        float As[16][64];
        float Bs[16][64];
    } d;
};

__global__ __launch_bounds__(256, 1) void fused_kernel(const float* __restrict__ hs,
                                                       const float* __restrict__ ht,
                                                       const float* __restrict__ WL,
                                                       const float* __restrict__ bL,
                                                       float* __restrict__ out) {
    __shared__ __align__(16) SmemU sm;

    const int tid = threadIdx.x;

    if (blockIdx.x >= NWIDE) {
        // ------------------ deep path tile ------------------
        const int t  = blockIdx.x - NWIDE;
        const int m0 = (t & 15) * 64;
        const int n0 = (t >> 4) * 64;
        const int ty = tid >> 4;
        const int tx = tid & 15;

        float acc[4][4] = {};

        for (int kk = 0; kk < 768; kk += 16) {
#pragma unroll
            for (int l = 0; l < 4; l++) {
                int i = tid + l * 256;
                int r = i >> 4;
                int c = i & 15;
                int k = kk + c;
                float av = (k < 384) ? hs[(size_t)(m0 + r) * 384 + k]
                                     : ht[(size_t)(m0 + r) * 384 + (k - 384)];
                sm.d.As[c][r] = av;
                sm.d.Bs[c][r] = WL[(size_t)(n0 + r) * 768 + k];
            }
            __syncthreads();
#pragma unroll
            for (int k = 0; k < 16; k++) {
                float4 a4 = *reinterpret_cast<const float4*>(&sm.d.As[k][ty * 4]);
                float4 b4 = *reinterpret_cast<const float4*>(&sm.d.Bs[k][tx * 4]);
                float a[4] = {a4.x, a4.y, a4.z, a4.w};
                float b[4] = {b4.x, b4.y, b4.z, b4.w};
#pragma unroll
                for (int i2 = 0; i2 < 4; i2++)
#pragma unroll
                    for (int j = 0; j < 4; j++) acc[i2][j] += a[i2] * b[j];
            }
            __syncthreads();
        }

#pragma unroll
        for (int i2 = 0; i2 < 4; i2++) {
            int m = m0 + ty * 4 + i2;
#pragma unroll
            for (int j = 0; j < 4; j++) {
                int n = n0 + tx * 4 + j;
                out[(size_t)m * 1536 + n] = acc[i2][j] + bL[n];
            }
        }
        return;
    }

    // ------------------ wide unit ------------------
    const int wid  = tid >> 5;
    const int lane = tid & 31;

    // blockIdx = ((ksl*16 + nt)*8 + mt): consecutive ids share the B slice
    const int mt   = blockIdx.x & 7;
    const int rest = blockIdx.x >> 3;
    const int nt   = rest & 15;
    const int ksl  = rest >> 4;
    const int n0   = nt * 48;
    const int p0   = ksl * PSLICE;
    const int CBEG = p0 * 6;
    const int CEND = (p0 + PSLICE) * 6;

    // this thread's two A rows (mma m16n8k16 fragment rows)
    const int r0 = mt * 128 + wid * 16 + (lane >> 2);
    const int r1 = r0 + 8;
    const int qo = 2 * (lane & 3);           // fragment k offset within k16

    const uint32_t ring0 = smem_u32(sm.w.ring[0]);
    const uint32_t mb0   = smem_u32(&sm.w.mbar[0]);

    if (tid == 0) {
#pragma unroll
        for (int s = 0; s < DEPTH; s++) MBAR_INIT(mb0 + s * 8, 1);
    }
    FENCE_PROXY_ASYNC();
    __syncthreads();

    // B tile source base for this n-tile (tiled+swizzled layout)
    const char* Wt = reinterpret_cast<const char*>(g_W2h) + (size_t)nt * NCHUNK * TILEB;

    // prologue: prefetch chunks CBEG..CBEG+PF-1 into slots 0..PF-1
    if (tid == 0) {
#pragma unroll
        for (int c = 0; c < PF; c++) {
            MBAR_EXPECT_TX(mb0 + c * 8, TILEB);
            bulk_copy(ring0 + c * TILEB, Wt + (size_t)(CBEG + c) * TILEB,
                      TILEB, mb0 + c * 8);
        }
    }

    // ---- resident ht fragments in registers: 2 rows x 24 blocks x 2 half2 ----
    __half2 htA[48], htB[48];
    {
        const float* htr0 = ht + (size_t)r0 * Dd;
        const float* htr1 = ht + (size_t)r1 * Dd;
#pragma unroll
        for (int blk = 0; blk < 24; blk++) {
            float2 f;
            f = *reinterpret_cast<const float2*>(htr0 + blk * 16 + qo);
            htA[blk * 2 + 0] = __floats2half2_rn(f.x, f.y);
            f = *reinterpret_cast<const float2*>(htr0 + blk * 16 + qo + 8);
            htA[blk * 2 + 1] = __floats2half2_rn(f.x, f.y);
            f = *reinterpret_cast<const float2*>(htr1 + blk * 16 + qo);
            htB[blk * 2 + 0] = __floats2half2_rn(f.x, f.y);
            f = *reinterpret_cast<const float2*>(htr1 + blk * 16 + qo + 8);
            htB[blk * 2 + 1] = __floats2half2_rn(f.x, f.y);
        }
    }

    float acc[6][4];
#pragma unroll
    for (int t = 0; t < 6; t++)
#pragma unroll
        for (int c = 0; c < 4; c++) acc[t][c] = 0.0f;

    // ldmatrix lane addressing (swizzled layout): row base + seg^row XOR
    const uint32_t rowoff = (uint32_t)((lane & 7) * 128);
    const uint32_t x0 = (uint32_t)((((lane >> 3)    ) ^ (lane & 7)) * 16);
    const uint32_t x1 = (uint32_t)((((lane >> 3) + 4) ^ (lane & 7)) * 16);

    const float* hsr0 = hs + (size_t)r0 * Dd;
    const float* hsr1 = hs + (size_t)r1 * Dd;

    // ---- main loop: 24 p values x 6 chunks of 64 q ----
    for (int pp = 0; pp < PSLICE; pp++) {
        const int p = p0 + pp;
        __half2 h0 = __half2half2(__float2half_rn(__ldg(hsr0 + p)));
        __half2 h1 = __half2half2(__float2half_rn(__ldg(hsr1 + p)));
        const uint32_t par = (uint32_t)(pp & 1);

#pragma unroll
        for (int c2 = 0; c2 < 6; c2++) {
            const int i = p * 6 + c2;            // global chunk; i % 6 == c2

            // all warps done with chunk i-1 => slot (i-1)%6 reusable
            __syncthreads();

            if (tid == 0) {
                int nc = i + PF;
                if (nc < CEND) {
                    int sl = (c2 + PF) % DEPTH;  // == nc % 6
                    MBAR_EXPECT_TX(mb0 + sl * 8, TILEB);
                    bulk_copy(ring0 + sl * TILEB, Wt + (size_t)nc * TILEB,
                              TILEB, mb0 + sl * 8);
                }
            }

            // A fragments for 4 k16-steps (pure register math)
            uint32_t a[4][4];
#pragma unroll
            for (int s = 0; s < 4; s++) {
                const int blk = c2 * 4 + s;
                a[s][0] = h2u(__hmul2(h0, htA[blk * 2 + 0]));  // row r0, k lo
                a[s][1] = h2u(__hmul2(h1, htB[blk * 2 + 0]));  // row r1, k lo
                a[s][2] = h2u(__hmul2(h0, htA[blk * 2 + 1]));  // row r0, k hi
                a[s][3] = h2u(__hmul2(h1, htB[blk * 2 + 1]));  // row r1, k hi
            }

            // wait B tile for chunk i
            mbar_wait(mb0 + c2 * 8, par);

            const uint32_t sbase = ring0 + (uint32_t)(c2 * TILEB) + rowoff;
#pragma unroll
            for (int t = 0; t < 6; t++) {
                uint32_t b0, b1, b2, b3, b4, b5, b6, b7;
                LDSM_X4(b0, b1, b2, b3, sbase + (uint32_t)(t * 1024) + x0); // ksteps 0,1
                LDSM_X4(b4, b5, b6, b7, sbase + (uint32_t)(t * 1024) + x1); // ksteps 2,3
                MMA16816(acc[t], a[0][0], a[0][1], a[0][2], a[0][3], b0, b1);
                MMA16816(acc[t], a[1][0], a[1][1], a[1][2], a[1][3], b2, b3);
                MMA16816(acc[t], a[2][0], a[2][1], a[2][2], a[2][3], b4, b5);
                MMA16816(acc[t], a[3][0], a[3][1], a[3][2], a[3][3], b6, b7);
            }
        }
    }

    // ---- epilogue: store f32 partial into g_part[ksl] (deterministic) ----
    float* pb = g_part + (size_t)ksl * (1024 * 768);
#pragma unroll
    for (int t = 0; t < 6; t++) {
        const int n = n0 + t * 8 + qo;
        *reinterpret_cast<float2*>(pb + (size_t)r0 * 768 + n) =
            make_float2(acc[t][0], acc[t][1]);
        *reinterpret_cast<float2*>(pb + (size_t)r1 * 768 + n) =
            make_float2(acc[t][2], acc[t][3]);
    }
}

// ===========================================================================
// Kernel 3: out[:,768:1536] = bias + sum over 16 K-slices of g_part
// grid = 768, block = 256; one float4 per thread (196608 float4 elements)
// ===========================================================================
__global__ __launch_bounds__(256) void reduce_kernel(const float* __restrict__ bL2,
                                                     float* __restrict__ out) {
    const int e4 = blockIdx.x * 256 + threadIdx.x;   // 0..196607
    const int b  = e4 / 192;                          // row
    const int n4 = e4 - b * 192;                      // float4 col
    const int n  = n4 * 4;

    float4 s = *reinterpret_cast<const float4*>(bL2 + n);
#pragma unroll
    for (int k = 0; k < KSPLIT; k++) {
        const float4 v = *reinterpret_cast<const float4*>(
            g_part + (size_t)k * (1024 * 768) + (size_t)b * 768 + n);
        s.x += v.x; s.y += v.y; s.z += v.z; s.w += v.w;
    }
    *reinterpret_cast<float4*>(out + (size_t)b * 1536 + 768 + n) = s;
}

// ===========================================================================
// kernel_launch
// Inputs (metadata order): hspatial, htext, W_L, b_L, W_L2, b_L2. Output f32.
// ===========================================================================
extern "C" void kernel_launch(void* const* d_in, const int* in_sizes, int n_in,
                              void* d_out, int out_size) {
    const float* hs  = (const float*)d_in[0];
    const float* ht  = (const float*)d_in[1];
    const float* WL  = (const float*)d_in[2];
    const float* bL  = (const float*)d_in[3];
    const float* WL2 = (const float*)d_in[4];
    const float* bL2 = (const float*)d_in[5];
    float* out = (float*)d_out;

    // 1) W_L2 -> fp16 scratch, tiled+swizzled (pure streaming, ~99 us)
    convert_kernel<<<2048, 256>>>(WL2);

    // 2) fused: 2048 wide K-slice units (HMMA) + 192 deep tiles
    fused_kernel<<<NWIDE + NDEEP, 256>>>(hs, ht, WL, bL, out);

    // 3) reduce K-slice partials + bias
    reduce_kernel<<<768, 256>>>(bL2, out);
}

// round 15
// speedup vs baseline: 2.1084x; 1.1247x over previous
#include <cuda_runtime.h>
#include <cuda_fp16.h>
#include <stdint.h>

// ===========================================================================
// Problem constants
// ===========================================================================
static constexpr int  Dd    = 384;
static constexpr long KTOT  = 147456;             // D*D

// Wide GEMM tiling (legacy HMMA path: mma.sync.m16n8k16, f32 accum)
static constexpr int NCHUNK = 2304;               // KTOT / 64
static constexpr int DEPTH  = 6;                  // B ring depth (== chunks per p)
static constexpr int PF     = 5;                  // prefetch distance
static constexpr int TILEB  = 48 * 128;           // 6144 B per B tile (contiguous)

// K-split: 16 slices of 24 p-values (144 chunks) each
static constexpr int KSPLIT = 16;
static constexpr int PSLICE = Dd / KSPLIT;        // 24
static constexpr int NWIDE  = 8 * 16 * KSPLIT;    // 2048 wide units

// fp16 copy of W_L2, TILED+SWIZZLED layout:
//   tile (T = n/48, c = chunk) at byte offset (T*NCHUNK + c)*6144
//   within tile: row r (=n%48), 16B seg s (=k/8 within chunk):
//   offset = r*128 + ((s ^ (r&7)) * 16)
__device__ __align__(16) __half g_W2h[113246208];

// per-K-slice partial accumulators (deterministic, no atomics): [16][1024][768]
__device__ __align__(16) float g_part[KSPLIT * 1024 * 768];

// ===========================================================================
// PTX helpers (baseline compute_103 features only: sm_90-era, no 'a')
// ===========================================================================
static __device__ __forceinline__ uint32_t smem_u32(const void* p) {
    uint32_t a;
    asm("{ .reg .u64 t; cvta.to.shared.u64 t, %1; cvt.u32.u64 %0, t; }" : "=r"(a) : "l"(p));
    return a;
}

#define MBAR_INIT(mbar, cnt) \
    asm volatile("mbarrier.init.shared.b64 [%0], %1;" \
                 :: "r"((uint32_t)(mbar)), "r"((uint32_t)(cnt)) : "memory")

#define MBAR_EXPECT_TX(mbar, bytes) \
    asm volatile("mbarrier.arrive.expect_tx.shared.b64 _, [%0], %1;" \
                 :: "r"((uint32_t)(mbar)), "r"((uint32_t)(bytes)) : "memory")

#define MBAR_ARRIVE(mbar) \
    asm volatile("mbarrier.arrive.shared.b64 _, [%0];" \
                 :: "r"((uint32_t)(mbar)) : "memory")

static __device__ __forceinline__ void mbar_wait(uint32_t mbar, uint32_t parity) {
    asm volatile(
        "{\n\t.reg .pred P;\n\t"
        "WL%=:\n\t"
        "mbarrier.try_wait.parity.acquire.cta.shared::cta.b64 P, [%0], %1;\n\t"
        "@!P bra WL%=;\n\t"
        "}"
        :: "r"(mbar), "r"(parity) : "memory");
}

static __device__ __forceinline__ void bulk_copy(uint32_t dst_smem, const void* src,
                                                 uint32_t bytes, uint32_t mbar) {
    asm volatile(
        "cp.async.bulk.shared::cta.global.mbarrier::complete_tx::bytes [%0], [%1], %2, [%3];"
        :: "r"(dst_smem), "l"(src), "r"(bytes), "r"(mbar) : "memory");
}

#define FENCE_PROXY_ASYNC() asm volatile("fence.proxy.async.shared::cta;" ::: "memory")

#define LDSM_X4(b0, b1, b2, b3, addr) \
    asm volatile("ldmatrix.sync.aligned.m8n8.x4.shared.b16 {%0,%1,%2,%3}, [%4];" \
                 : "=r"(b0), "=r"(b1), "=r"(b2), "=r"(b3) : "r"(addr))

#define MMA16816(d, a0, a1, a2, a3, b0, b1) \
    asm volatile("mma.sync.aligned.m16n8k16.row.col.f32.f16.f16.f32 " \
                 "{%0,%1,%2,%3}, {%4,%5,%6,%7}, {%8,%9}, {%0,%1,%2,%3};" \
                 : "+f"((d)[0]), "+f"((d)[1]), "+f"((d)[2]), "+f"((d)[3]) \
                 : "r"(a0), "r"(a1), "r"(a2), "r"(a3), "r"(b0), "r"(b1))

static __device__ __forceinline__ uint32_t h2u(__half2 v) {
    return *reinterpret_cast<uint32_t*>(&v);
}

// ===========================================================================
// Kernel 1: W_L2 f32 -> f16, TILED+SWIZZLED layout (pure streaming, 32 regs,
// measured 99 us @ 82% HBM peak — keep isolated, never fuse into it)
// ===========================================================================
__global__ __launch_bounds__(256) void convert_kernel(const float* __restrict__ W) {
    const long total = 768L * (KTOT / 8);          // 16B segs
    const long stride = (long)gridDim.x * blockDim.x;
    for (long g = (long)blockIdx.x * blockDim.x + threadIdx.x; g < total; g += stride) {
        int  n  = (int)(g / 18432);                // 18432 = KTOT/8
        int  ks = (int)(g - (long)n * 18432);
        int  c  = ks >> 3;
        int  s  = ks & 7;
        int  T  = n / 48;
        int  r  = n - T * 48;

        const float4* src = reinterpret_cast<const float4*>(
            W + (size_t)n * KTOT + ((size_t)c << 6) + (s << 3));
        float4 a = src[0];
        float4 b = src[1];
        uint4 v;
        v.x = h2u(__floats2half2_rn(a.x, a.y));
        v.y = h2u(__floats2half2_rn(a.z, a.w));
        v.z = h2u(__floats2half2_rn(b.x, b.y));
        v.w = h2u(__floats2half2_rn(b.z, b.w));

        size_t dst = (size_t)(T * NCHUNK + c) * TILEB
                   + (size_t)r * 128 + (size_t)((s ^ (r & 7)) << 4);
        *reinterpret_cast<uint4*>(reinterpret_cast<char*>(g_W2h) + dst) = v;
    }
}

// ===========================================================================
// Kernel 2: wide units (m-tile 128 x n-tile 48 x K-slice of 24 p-values).
//   A generated in registers; B via ONE cp.async.bulk per 64-k chunk.
//   Producer/consumer mbarrier pipeline — NO block barrier in the main loop:
//     full[s]  (count 1 + tx): bulk-copy completion for the slot
//     empty[s] (count 8): one arrive per warp after it finishes the chunk
//   f32 partials -> g_part[ksl] (deterministic, no atomics).
// ===========================================================================
__global__ __launch_bounds__(256, 1) void wide_kernel(const float* __restrict__ hs,
                                                      const float* __restrict__ ht) {
    __shared__ __align__(16) char ring[DEPTH][TILEB];        // 36864 B
    __shared__ __align__(8)  unsigned long long mbar[2 * DEPTH];

    const int tid  = threadIdx.x;
    const int wid  = tid >> 5;
    const int lane = tid & 31;

    // blockIdx = ((ksl*16 + nt)*8 + mt): consecutive ids share the B slice
    const int mt   = blockIdx.x & 7;
    const int rest = blockIdx.x >> 3;
    const int nt   = rest & 15;
    const int ksl  = rest >> 4;
    const int n0   = nt * 48;
    const int p0   = ksl * PSLICE;
    const int CBEG = p0 * 6;
    const int CEND = (p0 + PSLICE) * 6;

    // this thread's two A rows (mma m16n8k16 fragment rows)
    const int r0 = mt * 128 + wid * 16 + (lane >> 2);
    const int r1 = r0 + 8;
    const int qo = 2 * (lane & 3);           // fragment k offset within k16

    const uint32_t ring0 = smem_u32(ring[0]);
    const uint32_t fmb0  = smem_u32(&mbar[0]);          // full[0..5]
    const uint32_t emb0  = fmb0 + DEPTH * 8;            // empty[0..5]

    if (tid == 0) {
#pragma unroll
        for (int s = 0; s < DEPTH; s++) {
            MBAR_INIT(fmb0 + s * 8, 1);
            MBAR_INIT(emb0 + s * 8, 8);
        }
    }
    FENCE_PROXY_ASYNC();
    __syncthreads();

    // B tile source base for this n-tile (tiled+swizzled layout)
    const char* Wt = reinterpret_cast<const char*>(g_W2h) + (size_t)nt * NCHUNK * TILEB;

    // prologue: prefetch chunks CBEG..CBEG+PF-1 into slots 0..PF-1 (all fresh)
    if (tid == 0) {
#pragma unroll
        for (int c = 0; c < PF; c++) {
            MBAR_EXPECT_TX(fmb0 + c * 8, TILEB);
            bulk_copy(ring0 + c * TILEB, Wt + (size_t)(CBEG + c) * TILEB,
                      TILEB, fmb0 + c * 8);
        }
    }

    // ---- resident ht fragments in registers: 2 rows x 24 blocks x 2 half2 ----
    __half2 htA[48], htB[48];
    {
        const float* htr0 = ht + (size_t)r0 * Dd;
        const float* htr1 = ht + (size_t)r1 * Dd;
#pragma unroll
        for (int blk = 0; blk < 24; blk++) {
            float2 f;
            f = *reinterpret_cast<const float2*>(htr0 + blk * 16 + qo);
            htA[blk * 2 + 0] = __floats2half2_rn(f.x, f.y);
            f = *reinterpret_cast<const float2*>(htr0 + blk * 16 + qo + 8);
            htA[blk * 2 + 1] = __floats2half2_rn(f.x, f.y);
            f = *reinterpret_cast<const float2*>(htr1 + blk * 16 + qo);
            htB[blk * 2 + 0] = __floats2half2_rn(f.x, f.y);
            f = *reinterpret_cast<const float2*>(htr1 + blk * 16 + qo + 8);
            htB[blk * 2 + 1] = __floats2half2_rn(f.x, f.y);
        }
    }

    float acc[6][4];
#pragma unroll
    for (int t = 0; t < 6; t++)
#pragma unroll
        for (int c = 0; c < 4; c++) acc[t][c] = 0.0f;

    // ldmatrix lane addressing (swizzled layout): row base + seg^row XOR
    const uint32_t rowoff = (uint32_t)((lane & 7) * 128);
    const uint32_t x0 = (uint32_t)((((lane >> 3)    ) ^ (lane & 7)) * 16);
    const uint32_t x1 = (uint32_t)((((lane >> 3) + 4) ^ (lane & 7)) * 16);

    const float* hsr0 = hs + (size_t)r0 * Dd;
    const float* hsr1 = hs + (size_t)r1 * Dd;

    // ---- main loop: 24 p values x 6 chunks of 64 q (no block barrier) ----
    for (int pp = 0; pp < PSLICE; pp++) {
        const int p = p0 + pp;
        __half2 h0 = __half2half2(__float2half_rn(__ldg(hsr0 + p)));
        __half2 h1 = __half2half2(__float2half_rn(__ldg(hsr1 + p)));
        const uint32_t par = (uint32_t)(pp & 1);

#pragma unroll
        for (int c2 = 0; c2 < 6; c2++) {
            const int i = p * 6 + c2;            // global chunk; i % 6 == c2

            // A fragments for 4 k16-steps (pure register math, no waits)
            uint32_t a[4][4];
#pragma unroll
            for (int s = 0; s < 4; s++) {
                const int blk = c2 * 4 + s;
                a[s][0] = h2u(__hmul2(h0, htA[blk * 2 + 0]));  // row r0, k lo
                a[s][1] = h2u(__hmul2(h1, htB[blk * 2 + 0]));  // row r1, k lo
                a[s][2] = h2u(__hmul2(h0, htA[blk * 2 + 1]));  // row r0, k hi
                a[s][3] = h2u(__hmul2(h1, htB[blk * 2 + 1]));  // row r1, k hi
            }

            // producer: issue chunk i+PF into slot (c2+PF)%6 once that slot's
            // previous consumers have all arrived on empty[]
            if (tid == 0) {
                const int nc = i + PF;
                if (nc < CEND) {
                    const int sl = (c2 + PF) % DEPTH;   // == nc % 6
                    if (!(pp == 0 && c2 == 0)) {
                        // empty parity: (use#-1)&1 -> par for c2>=1, par^1 for c2==0
                        const uint32_t ep = (c2 == 0) ? (par ^ 1u) : par;
                        mbar_wait(emb0 + sl * 8, ep);
                    }
                    MBAR_EXPECT_TX(fmb0 + sl * 8, TILEB);
                    bulk_copy(ring0 + sl * TILEB, Wt + (size_t)nc * TILEB,
                              TILEB, fmb0 + sl * 8);
                }
            }

            // consumer: wait B tile for chunk i (phase = pp)
            mbar_wait(fmb0 + c2 * 8, par);

            const uint32_t sbase = ring0 + (uint32_t)(c2 * TILEB) + rowoff;
#pragma unroll
            for (int t = 0; t < 6; t++) {
                uint32_t b0, b1, b2, b3, b4, b5, b6, b7;
                LDSM_X4(b0, b1, b2, b3, sbase + (uint32_t)(t * 1024) + x0); // ksteps 0,1
                LDSM_X4(b4, b5, b6, b7, sbase + (uint32_t)(t * 1024) + x1); // ksteps 2,3
                MMA16816(acc[t], a[0][0], a[0][1], a[0][2], a[0][3], b0, b1);
                MMA16816(acc[t], a[1][0], a[1][1], a[1][2], a[1][3], b2, b3);
                MMA16816(acc[t], a[2][0], a[2][1], a[2][2], a[2][3], b4, b5);
                MMA16816(acc[t], a[3][0], a[3][1], a[3][2], a[3][3], b6, b7);
            }

            // this warp is done reading slot c2 for this phase
            if (lane == 0) MBAR_ARRIVE(emb0 + c2 * 8);
        }
    }

    // ---- epilogue: store f32 partial into g_part[ksl] (deterministic) ----
    float* pb = g_part + (size_t)ksl * (1024 * 768);
#pragma unroll
    for (int t = 0; t < 6; t++) {
        const int n = n0 + t * 8 + qo;
        *reinterpret_cast<float2*>(pb + (size_t)r0 * 768 + n) =
            make_float2(acc[t][0], acc[t][1]);
        *reinterpret_cast<float2*>(pb + (size_t)r1 * 768 + n) =
            make_float2(acc[t][2], acc[t][3]);
    }
}

// ===========================================================================
// Kernel 3: deep path g = cat(hs,ht) @ W_L^T + b_L  (exact f32, 64x64 tiles)
// grid = (16, 12), 256 threads — standalone to avoid codegen contamination
// ===========================================================================
__global__ __launch_bounds__(256) void deep_kernel(const float* __restrict__ hs,
                                                   const float* __restrict__ ht,
                                                   const float* __restrict__ WL,
                                                   const float* __restrict__ bL,
                                                   float* __restrict__ out) {
    __shared__ float As[16][64];
    __shared__ float Bs[16][64];
    const int tid = threadIdx.x;
    const int m0 = blockIdx.x * 64;
    const int n0 = blockIdx.y * 64;
    const int ty = tid >> 4;
    const int tx = tid & 15;

    float acc[4][4] = {};

    for (int kk = 0; kk < 768; kk += 16) {
#pragma unroll
        for (int l = 0; l < 4; l++) {
            int i = tid + l * 256;
            int r = i >> 4;
            int c = i & 15;
            int k = kk + c;
            float av = (k < 384) ? hs[(size_t)(m0 + r) * 384 + k]
                                 : ht[(size_t)(m0 + r) * 384 + (k - 384)];
            As[c][r] = av;
            Bs[c][r] = WL[(size_t)(n0 + r) * 768 + k];
        }
        __syncthreads();
#pragma unroll
        for (int k = 0; k < 16; k++) {
            float4 a4 = *reinterpret_cast<const float4*>(&As[k][ty * 4]);
            float4 b4 = *reinterpret_cast<const float4*>(&Bs[k][tx * 4]);
            float a[4] = {a4.x, a4.y, a4.z, a4.w};
            float b[4] = {b4.x, b4.y, b4.z, b4.w};
#pragma unroll
            for (int i2 = 0; i2 < 4; i2++)
#pragma unroll
                for (int j = 0; j < 4; j++) acc[i2][j] += a[i2] * b[j];
        }
        __syncthreads();
    }

#pragma unroll
    for (int i2 = 0; i2 < 4; i2++) {
        int m = m0 + ty * 4 + i2;
#pragma unroll
        for (int j = 0; j < 4; j++) {
            int n = n0 + tx * 4 + j;
            out[(size_t)m * 1536 + n] = acc[i2][j] + bL[n];
        }
    }
}

// ===========================================================================
// Kernel 4: out[:,768:1536] = bias + sum over 16 K-slices of g_part
// grid = 768, block = 256; one float4 per thread (196608 float4 elements)
// ===========================================================================
__global__ __launch_bounds__(256) void reduce_kernel(const float* __restrict__ bL2,
                                                     float* __restrict__ out) {
    const int e4 = blockIdx.x * 256 + threadIdx.x;   // 0..196607
    const int b  = e4 / 192;                          // row
    const int n4 = e4 - b * 192;                      // float4 col
    const int n  = n4 * 4;

    float4 s = *reinterpret_cast<const float4*>(bL2 + n);
#pragma unroll
    for (int k = 0; k < KSPLIT; k++) {
        const float4 v = *reinterpret_cast<const float4*>(
            g_part + (size_t)k * (1024 * 768) + (size_t)b * 768 + n);
        s.x += v.x; s.y += v.y; s.z += v.z; s.w += v.w;
    }
    *reinterpret_cast<float4*>(out + (size_t)b * 1536 + 768 + n) = s;
}

// ===========================================================================
// kernel_launch
// Inputs (metadata order): hspatial, htext, W_L, b_L, W_L2, b_L2. Output f32.
// ===========================================================================
extern "C" void kernel_launch(void* const* d_in, const int* in_sizes, int n_in,
                              void* d_out, int out_size) {
    const float* hs  = (const float*)d_in[0];
    const float* ht  = (const float*)d_in[1];
    const float* WL  = (const float*)d_in[2];
    const float* bL  = (const float*)d_in[3];
    const float* WL2 = (const float*)d_in[4];
    const float* bL2 = (const float*)d_in[5];
    float* out = (float*)d_out;

    // 1) W_L2 -> fp16 scratch, tiled+swizzled (pure streaming, ~99 us)
    convert_kernel<<<2048, 256>>>(WL2);

    // 2) wide path: 2048 K-slice units, mbarrier producer/consumer pipeline
    wide_kernel<<<NWIDE, 256>>>(hs, ht);

    // 3) deep path (exact f32, standalone)
    dim3 dgrid(16, 12);
    deep_kernel<<<dgrid, 256>>>(hs, ht, WL, bL, out);

    // 4) reduce K-slice partials + bias
    reduce_kernel<<<768, 256>>>(bL2, out);
}